// round 2
// baseline (speedup 1.0000x reference)
#include <cuda_runtime.h>
#include <math.h>

#define NE 160000
#define NN 10000

// ---------------- device scratch ----------------
__device__ float g_H[NE * 64];     // per-edge MLP hidden (after 3 silu layers)
__device__ float g_sh[NE * 9];     // per-edge spherical harmonics
__device__ float g_cnt[NN];        // per-node edge counts
__device__ float g_w3j[363];       // normalized Wigner-3j tables, 11 paths

// ---------------- path metadata ----------------
// PATHS = [(0,0,0),(0,1,1),(0,2,2),(1,0,1),(1,1,0),(1,1,2),(1,2,1),(2,0,2),(2,1,1),(2,2,0),(2,2,2)]
__device__ constexpr int PL1[11]   = {0,0,0,1,1,1,1,2,2,2,2};
__device__ constexpr int PL2[11]   = {0,1,2,0,1,1,2,0,1,2,2};
__device__ constexpr int PL3[11]   = {0,1,2,1,0,2,1,2,1,0,2};
__device__ constexpr int PD3[11]   = {1,3,5,3,1,5,3,5,3,1,5};
__device__ constexpr int W3OFF[11] = {0,1,10,35,44,53,98,143,168,213,238};     // sizes d1*d2*d3
__device__ constexpr int TOFF[11]  = {0,16,64,144,192,208,288,336,416,464,480}; // cum 16*d3 (total 560)
__device__ constexpr int AROW[11]  = {0,1,4,1,0,4,1,4,1,0,4};                   // acc row base per l3
// alpha = sqrt(DIMS[l3]) / sqrt(FAN_IN[l3]); FAN_IN = [48,64,64]
__device__ constexpr float ALPHA[11] = {
    0.14433756729740643f, 0.21650635094610965f, 0.27950849718747373f,
    0.21650635094610965f, 0.14433756729740643f, 0.27950849718747373f,
    0.21650635094610965f, 0.27950849718747373f, 0.21650635094610965f,
    0.14433756729740643f, 0.27950849718747373f};
__device__ constexpr int XO[3]     = {0,1,4};                  // offsets into 9-slot l-blocks
__device__ constexpr int FLATB[9]  = {0,16,32,48,64,80,96,112,128}; // flat msg offset per acc row

// ---------------- W3J init (exact FP64 replica of reference construction) ----------------
__device__ double dfact(int n) { double r = 1.0; for (int i = 2; i <= n; ++i) r *= (double)i; return r; }

__device__ double su2_cg(int j1, int m1, int j2, int m2, int j3, int m3) {
    if (m1 + m2 != m3) return 0.0;
    int vmin = 0;
    if (-j1 + j2 + m3 > vmin) vmin = -j1 + j2 + m3;
    if (-j1 + m1 > vmin)      vmin = -j1 + m1;
    int vmax = j2 + j3 + m1;
    if (j3 - j1 + j2 < vmax) vmax = j3 - j1 + j2;
    if (j3 + m3 < vmax)      vmax = j3 + m3;
    double C = sqrt((2.0 * j3 + 1.0) * dfact(j3 + j1 - j2) * dfact(j3 - j1 + j2) * dfact(j1 + j2 - j3)
                    / dfact(j1 + j2 + j3 + 1)
                    * dfact(j3 + m3) * dfact(j3 - m3)
                    / (dfact(j1 - m1) * dfact(j1 + m1) * dfact(j2 - m2) * dfact(j2 + m2)));
    double S = 0.0;
    for (int v = vmin; v <= vmax; ++v) {
        double sgn = ((v + j2 + m2) & 1) ? -1.0 : 1.0;
        S += sgn / dfact(v) * dfact(j2 + j3 + m1 - v) * dfact(j1 - m1 + v)
             / dfact(j3 - j1 + j2 - v) / dfact(j3 + m3 - v) / dfact(v + j1 - j2 - m3);
    }
    return C * S;
}

__device__ void qelem(int l, int r, int c, double& re, double& im) {
    int m = r - l;
    double vr = 0.0, vi = 0.0;
    const double is2 = 0.70710678118654752440;
    if (m < 0) {
        if (c == l - m) vr = is2;    // q[l+m, l+|m|] = 1/sqrt2
        if (c == l + m) vi = -is2;   // q[l+m, l-|m|] = -i/sqrt2
    } else if (m == 0) {
        if (c == l) vr = 1.0;
    } else {
        double sg = (m & 1) ? -1.0 : 1.0;
        if (c == l + m) vr = sg * is2;
        if (c == l - m) vi = sg * is2;
    }
    // multiply by (-i)^l
    if (l == 1) { double t = vr; vr = vi; vi = -t; }
    else if (l == 2) { vr = -vr; vi = -vi; }
    re = vr; im = vi;
}

__global__ void k_init_w3j() {
    int p = threadIdx.x;
    if (p >= 11) return;
    const int l1 = PL1[p], l2 = PL2[p], l3 = PL3[p];
    const int d1 = 2 * l1 + 1, d2 = 2 * l2 + 1, d3 = 2 * l3 + 1;
    double vals[125];
    double n2 = 0.0;
    for (int j = 0; j < d1; ++j)
        for (int l = 0; l < d2; ++l)
            for (int m = 0; m < d3; ++m) {
                double sre = 0.0;
                for (int i = 0; i < d1; ++i)
                    for (int k = 0; k < d2; ++k)
                        for (int n = 0; n < d3; ++n) {
                            double cg = su2_cg(l1, i - l1, l2, k - l2, l3, n - l3);
                            if (cg == 0.0) continue;
                            double q1r, q1i, q2r, q2i, q3r, q3i;
                            qelem(l1, i, j, q1r, q1i);
                            qelem(l2, k, l, q2r, q2i);
                            qelem(l3, n, m, q3r, q3i);
                            q3i = -q3i; // conj(q(l3).T)[m,n] = conj(q(l3)[n,m])
                            double ar = q1r * q2r - q1i * q2i;
                            double ai = q1r * q2i + q1i * q2r;
                            sre += (ar * q3r - ai * q3i) * cg;
                        }
                vals[(j * d2 + l) * d3 + m] = sre;
                n2 += sre * sre;
            }
    double inv = 1.0 / sqrt(n2);
    for (int t = 0; t < d1 * d2 * d3; ++t)
        g_w3j[W3OFF[p] + t] = (float)(vals[t] * inv);
}

// ---------------- zero / count / divide ----------------
__global__ void k_zero(float* __restrict__ out) {
    int i = blockIdx.x * blockDim.x + threadIdx.x;
    if (i < NN * 144) out[i] = 0.0f;
    if (i < NN) g_cnt[i] = 0.0f;
}

__global__ void k_count(const int* __restrict__ edst) {
    int i = blockIdx.x * blockDim.x + threadIdx.x;
    if (i < NE) atomicAdd(&g_cnt[edst[i]], 1.0f);
}

__global__ void k_div(float* __restrict__ out) {
    int i = blockIdx.x * blockDim.x + threadIdx.x;
    if (i < NN * 144) {
        float c = g_cnt[i / 144];
        out[i] = out[i] / fmaxf(c, 1.0f);
    }
}

// ---------------- kernel A: geometry + radial + MLP(8->64->64->64) ----------------
__global__ void __launch_bounds__(256) k_edge_mlp(
    const float* __restrict__ pos, const int* __restrict__ batch,
    const int* __restrict__ esrc, const int* __restrict__ edst,
    const float* __restrict__ eshift, const float* __restrict__ cell,
    const float* __restrict__ w0, const float* __restrict__ b0,
    const float* __restrict__ w1, const float* __restrict__ b1,
    const float* __restrict__ w2, const float* __restrict__ b2)
{
    __shared__ float s_sh[4][9];
    __shared__ float s_emb[4][8];
    __shared__ float s_h[4][2][64];
    const int g = threadIdx.x >> 6;
    const int t = threadIdx.x & 63;
    const int e = blockIdx.x * 4 + g;   // NE % 4 == 0

    if (t == 0) {
        const int src = esrc[e], dst = edst[e];
        const int b = batch[src];
        const float s0 = eshift[e * 3 + 0], s1 = eshift[e * 3 + 1], s2 = eshift[e * 3 + 2];
        const float* C = cell + b * 9;
        float vx = pos[dst * 3 + 0] - pos[src * 3 + 0] + s0 * C[0] + s1 * C[3] + s2 * C[6];
        float vy = pos[dst * 3 + 1] - pos[src * 3 + 1] + s0 * C[1] + s1 * C[4] + s2 * C[7];
        float vz = pos[dst * 3 + 2] - pos[src * 3 + 2] + s0 * C[2] + s1 * C[5] + s2 * C[8];
        float r = sqrtf(vx * vx + vy * vy + vz * vz + 1e-12f);
        float ir = 1.0f / r;
        float x = vx * ir, y = vy * ir, z = vz * ir;
        const float s3c = 1.7320508075688772f;
        const float s15 = 3.8729833462074170f;
        const float s5  = 2.2360679774997896f;
        s_sh[g][0] = 1.0f;
        s_sh[g][1] = s3c * y;
        s_sh[g][2] = s3c * z;
        s_sh[g][3] = s3c * x;
        s_sh[g][4] = s15 * x * y;
        s_sh[g][5] = s15 * y * z;
        s_sh[g][6] = 0.5f * s5 * (3.0f * z * z - 1.0f);
        s_sh[g][7] = s15 * x * z;
        s_sh[g][8] = 0.5f * s15 * (x * x - y * y);
        float xr = fminf(fmaxf(r * (1.0f / 6.0f), 0.0f), 1.0f);
        float gate = (r <= 6.0f) ? 2.8284271247461903f : 0.0f; // sqrt(8) * cutoff
        #pragma unroll
        for (int jb = 0; jb < 8; ++jb) {
            float d = (xr - (float)jb * (1.0f / 7.0f)) * 7.0f;
            s_emb[g][jb] = expf(-0.5f * d * d) * gate;
        }
    }
    __syncthreads();

    float a = b0[t];
    #pragma unroll
    for (int c = 0; c < 8; ++c) a += s_emb[g][c] * w0[c * 64 + t];
    a = a / (1.0f + expf(-a));
    s_h[g][0][t] = a;
    __syncthreads();

    a = b1[t];
    #pragma unroll 8
    for (int c = 0; c < 64; ++c) a += s_h[g][0][c] * w1[c * 64 + t];
    a = a / (1.0f + expf(-a));
    s_h[g][1][t] = a;
    __syncthreads();

    a = b2[t];
    #pragma unroll 8
    for (int c = 0; c < 64; ++c) a += s_h[g][1][c] * w2[c * 64 + t];
    a = a / (1.0f + expf(-a));
    g_H[(size_t)e * 64 + t] = a;
    if (t < 9) g_sh[(size_t)e * 9 + t] = s_sh[g][t];
}

// ---------------- kernel B: fused weight-GEMM + tensor product + scatter ----------------
// Block = 256 threads, 16 edges. Thread mapping phase 3: tid = e*16 + s*4 + w4.
__global__ void __launch_bounds__(256) k_tp(
    const float* __restrict__ f_in,
    const int* __restrict__ esrc, const int* __restrict__ edst,
    const float* __restrict__ w3, const float* __restrict__ b3,
    float* __restrict__ out)
{
    __shared__ float4 sH[16][16];     // H[e][c] as float4 over c
    __shared__ float  ssh[16][9];
    __shared__ float  sT[16][560];    // alpha-scaled left contraction T[e][toff(p)+u*d3+k]
    __shared__ int    ssrc[16];
    __shared__ int    sdst[16];

    const int tid = threadIdx.x;
    const int e0 = blockIdx.x << 4;

    {
        const float4* gh = reinterpret_cast<const float4*>(g_H + (size_t)e0 * 64);
        reinterpret_cast<float4*>(sH)[tid] = gh[tid];      // 256 float4 = 16*64 floats
    }
    if (tid < 144) ssh[tid / 9][tid % 9] = g_sh[(size_t)e0 * 9 + tid];
    if (tid < 16) ssrc[tid] = esrc[e0 + tid];
    else if (tid < 32) sdst[tid - 16] = edst[e0 + tid - 16];
    __syncthreads();

    // ---- phase 2: T[e,u,(p,k)] = alpha * sum_{i,j} x1[e,i,u]*sh[e,j]*W3J[i,j,k]
    {
        const int e = tid >> 4, u = tid & 15;
        const float* x1 = f_in + (size_t)ssrc[e] * 144;
        float xall[9];
        xall[0] = x1[u];
        #pragma unroll
        for (int i = 0; i < 3; ++i) xall[1 + i] = x1[16 + i * 16 + u];
        #pragma unroll
        for (int i = 0; i < 5; ++i) xall[4 + i] = x1[64 + i * 16 + u];
        float sl[9];
        #pragma unroll
        for (int j = 0; j < 9; ++j) sl[j] = ssh[e][j];
        float* Te = sT[e];
        #pragma unroll
        for (int p = 0; p < 11; ++p) {
            const int l1 = PL1[p], l2 = PL2[p];
            const int d1 = 2 * l1 + 1, d2 = 2 * l2 + 1, d3 = PD3[p];
            float acc[5];
            #pragma unroll
            for (int k = 0; k < 5; ++k) acc[k] = 0.0f;
            const float* wj = g_w3j + W3OFF[p];
            #pragma unroll
            for (int i = 0; i < d1; ++i) {
                const float xi = xall[XO[l1] + i];
                #pragma unroll
                for (int j = 0; j < d2; ++j) {
                    const float xs = xi * sl[XO[l2] + j];
                    #pragma unroll
                    for (int k = 0; k < d3; ++k)
                        acc[k] += xs * __ldg(&wj[(i * d2 + j) * d3 + k]);
                }
            }
            #pragma unroll
            for (int k = 0; k < d3; ++k)
                Te[TOFF[p] + u * d3 + k] = ALPHA[p] * acc[k];
        }
    }
    __syncthreads();

    // ---- phase 3: msg[e, row, w] = sum_{p,u} T * (H·W3col + b3), vectorized over 4 w
    const int e  = tid >> 4;
    const int s  = (tid >> 2) & 3;
    const int w4 = tid & 3;
    float4 acc[9];
    #pragma unroll
    for (int a = 0; a < 9; ++a) acc[a] = make_float4(0.f, 0.f, 0.f, 0.f);
    const float*  Te = sT[e];
    const float4* H4 = &sH[e][0];

    #pragma unroll
    for (int p = 0; p < 11; ++p) {
        const int d3 = PD3[p];
        #pragma unroll 1
        for (int us = 0; us < 4; ++us) {
            const int u = s + us * 4;
            const int idx = p * 256 + u * 16 + (w4 << 2);
            float4 Wv = __ldg(reinterpret_cast<const float4*>(b3 + idx));
            const float* wp = w3 + idx;
            #pragma unroll 4
            for (int c4 = 0; c4 < 16; ++c4) {
                const float4 h = H4[c4];
                float4 wa;
                wa = __ldg(reinterpret_cast<const float4*>(wp + (c4 * 4 + 0) * 2816));
                Wv.x += h.x * wa.x; Wv.y += h.x * wa.y; Wv.z += h.x * wa.z; Wv.w += h.x * wa.w;
                wa = __ldg(reinterpret_cast<const float4*>(wp + (c4 * 4 + 1) * 2816));
                Wv.x += h.y * wa.x; Wv.y += h.y * wa.y; Wv.z += h.y * wa.z; Wv.w += h.y * wa.w;
                wa = __ldg(reinterpret_cast<const float4*>(wp + (c4 * 4 + 2) * 2816));
                Wv.x += h.z * wa.x; Wv.y += h.z * wa.y; Wv.z += h.z * wa.z; Wv.w += h.z * wa.w;
                wa = __ldg(reinterpret_cast<const float4*>(wp + (c4 * 4 + 3) * 2816));
                Wv.x += h.w * wa.x; Wv.y += h.w * wa.y; Wv.z += h.w * wa.z; Wv.w += h.w * wa.w;
            }
            #pragma unroll
            for (int k = 0; k < d3; ++k) {
                const float t = Te[TOFF[p] + u * d3 + k];
                const int a = AROW[p] + k;
                acc[a].x += t * Wv.x; acc[a].y += t * Wv.y;
                acc[a].z += t * Wv.z; acc[a].w += t * Wv.w;
            }
        }
    }

    // reduce the 4-way u-split across lanes differing in s (bits 2..3 of lane id)
    #pragma unroll
    for (int a = 0; a < 9; ++a) {
        #pragma unroll
        for (int off = 4; off <= 8; off <<= 1) {
            acc[a].x += __shfl_xor_sync(0xffffffffu, acc[a].x, off);
            acc[a].y += __shfl_xor_sync(0xffffffffu, acc[a].y, off);
            acc[a].z += __shfl_xor_sync(0xffffffffu, acc[a].z, off);
            acc[a].w += __shfl_xor_sync(0xffffffffu, acc[a].w, off);
        }
    }
    if (s == 0) {
        float* op = out + (size_t)sdst[e] * 144 + (w4 << 2);
        #pragma unroll
        for (int a = 0; a < 9; ++a) {
            atomicAdd(op + FLATB[a] + 0, acc[a].x);
            atomicAdd(op + FLATB[a] + 1, acc[a].y);
            atomicAdd(op + FLATB[a] + 2, acc[a].z);
            atomicAdd(op + FLATB[a] + 3, acc[a].w);
        }
    }
}

// ---------------- launch ----------------
extern "C" void kernel_launch(void* const* d_in, const int* in_sizes, int n_in,
                              void* d_out, int out_size)
{
    const float* f_in   = (const float*)d_in[0];
    const float* pos    = (const float*)d_in[1];
    // d_in[2] = A (unused by reference output)
    const int*   batch  = (const int*)d_in[3];
    const int*   esrc   = (const int*)d_in[4];
    const int*   edst   = (const int*)d_in[5];
    const float* eshift = (const float*)d_in[6];
    const float* cell   = (const float*)d_in[7];
    const float* w0 = (const float*)d_in[8];
    const float* b0 = (const float*)d_in[9];
    const float* w1 = (const float*)d_in[10];
    const float* b1 = (const float*)d_in[11];
    const float* w2 = (const float*)d_in[12];
    const float* b2 = (const float*)d_in[13];
    const float* w3 = (const float*)d_in[14];
    const float* b3 = (const float*)d_in[15];
    float* out = (float*)d_out;

    k_init_w3j<<<1, 32>>>();
    k_zero<<<(NN * 144 + 255) / 256, 256>>>(out);
    k_edge_mlp<<<NE / 4, 256>>>(pos, batch, esrc, edst, eshift, cell,
                                w0, b0, w1, b1, w2, b2);
    k_count<<<(NE + 255) / 256, 256>>>(edst);
    k_tp<<<NE / 16, 256>>>(f_in, esrc, edst, w3, b3, out);
    k_div<<<(NN * 144 + 255) / 256, 256>>>(out);
}

// round 3
// speedup vs baseline: 1.2342x; 1.2342x over previous
#include <cuda_runtime.h>
#include <math.h>

#define NE 160000
#define NN 10000
#define CH_E 32000           // edges per Wv chunk (5 chunks)
#define NCHUNK 5

// ---------------- device scratch ----------------
__device__ float g_H[64 * NE];               // MLP hidden, TRANSPOSED: [k][e]
__device__ float g_sh[NE * 9];               // spherical harmonics
__device__ float g_cnt[NN];                  // per-node edge counts
__device__ float g_w3j[363];                 // Wigner-3j tables
__device__ float g_Wv[(size_t)CH_E * 2816];  // chunk of per-edge weights

// ---------------- path metadata ----------------
__device__ constexpr int PL1[11]   = {0,0,0,1,1,1,1,2,2,2,2};
__device__ constexpr int PL2[11]   = {0,1,2,0,1,1,2,0,1,2,2};
__device__ constexpr int PD3[11]   = {1,3,5,3,1,5,3,5,3,1,5};
__device__ constexpr int W3OFF[11] = {0,1,10,35,44,53,98,143,168,213,238};
__device__ constexpr int TOFF[11]  = {0,16,64,144,192,208,288,336,416,464,480};
__device__ constexpr int AROW[11]  = {0,1,4,1,0,4,1,4,1,0,4};
__device__ constexpr float ALPHA[11] = {
    0.14433756729740643f, 0.21650635094610965f, 0.27950849718747373f,
    0.21650635094610965f, 0.14433756729740643f, 0.27950849718747373f,
    0.21650635094610965f, 0.27950849718747373f, 0.21650635094610965f,
    0.14433756729740643f, 0.27950849718747373f};
__device__ constexpr int XO[3] = {0,1,4};

// ---------------- f32x2 packed FMA helpers ----------------
__device__ __forceinline__ unsigned long long pk2(float x, float y) {
    unsigned long long r;
    asm("mov.b64 %0, {%1,%2};" : "=l"(r) : "f"(x), "f"(y));
    return r;
}
__device__ __forceinline__ void fma2(unsigned long long& d, unsigned long long a, unsigned long long b) {
    asm("fma.rn.f32x2 %0, %1, %2, %0;" : "+l"(d) : "l"(a), "l"(b));
}
__device__ __forceinline__ float2 up2(unsigned long long v) {
    float2 r;
    asm("mov.b64 {%0,%1}, %2;" : "=f"(r.x), "=f"(r.y) : "l"(v));
    return r;
}

// ---------------- W3J init (exact FP64 replica of reference construction) ----------------
__device__ double dfact(int n) { double r = 1.0; for (int i = 2; i <= n; ++i) r *= (double)i; return r; }

__device__ double su2_cg(int j1, int m1, int j2, int m2, int j3, int m3) {
    if (m1 + m2 != m3) return 0.0;
    int vmin = 0;
    if (-j1 + j2 + m3 > vmin) vmin = -j1 + j2 + m3;
    if (-j1 + m1 > vmin)      vmin = -j1 + m1;
    int vmax = j2 + j3 + m1;
    if (j3 - j1 + j2 < vmax) vmax = j3 - j1 + j2;
    if (j3 + m3 < vmax)      vmax = j3 + m3;
    double C = sqrt((2.0 * j3 + 1.0) * dfact(j3 + j1 - j2) * dfact(j3 - j1 + j2) * dfact(j1 + j2 - j3)
                    / dfact(j1 + j2 + j3 + 1)
                    * dfact(j3 + m3) * dfact(j3 - m3)
                    / (dfact(j1 - m1) * dfact(j1 + m1) * dfact(j2 - m2) * dfact(j2 + m2)));
    double S = 0.0;
    for (int v = vmin; v <= vmax; ++v) {
        double sgn = ((v + j2 + m2) & 1) ? -1.0 : 1.0;
        S += sgn / dfact(v) * dfact(j2 + j3 + m1 - v) * dfact(j1 - m1 + v)
             / dfact(j3 - j1 + j2 - v) / dfact(j3 + m3 - v) / dfact(v + j1 - j2 - m3);
    }
    return C * S;
}

__device__ void qelem(int l, int r, int c, double& re, double& im) {
    int m = r - l;
    double vr = 0.0, vi = 0.0;
    const double is2 = 0.70710678118654752440;
    if (m < 0) {
        if (c == l - m) vr = is2;
        if (c == l + m) vi = -is2;
    } else if (m == 0) {
        if (c == l) vr = 1.0;
    } else {
        double sg = (m & 1) ? -1.0 : 1.0;
        if (c == l + m) vr = sg * is2;
        if (c == l - m) vi = sg * is2;
    }
    if (l == 1) { double t = vr; vr = vi; vi = -t; }
    else if (l == 2) { vr = -vr; vi = -vi; }
    re = vr; im = vi;
}

__global__ void k_init_w3j() {
    int p = threadIdx.x;
    if (p >= 11) return;
    const int l1 = PL1[p], l2 = PL2[p];
    const int l3v[11] = {0,1,2,1,0,2,1,2,1,0,2};
    const int l3 = l3v[p];
    const int d1 = 2 * l1 + 1, d2 = 2 * l2 + 1, d3 = 2 * l3 + 1;
    double vals[125];
    double n2 = 0.0;
    for (int j = 0; j < d1; ++j)
        for (int l = 0; l < d2; ++l)
            for (int m = 0; m < d3; ++m) {
                double sre = 0.0;
                for (int i = 0; i < d1; ++i)
                    for (int k = 0; k < d2; ++k)
                        for (int n = 0; n < d3; ++n) {
                            double cg = su2_cg(l1, i - l1, l2, k - l2, l3, n - l3);
                            if (cg == 0.0) continue;
                            double q1r, q1i, q2r, q2i, q3r, q3i;
                            qelem(l1, i, j, q1r, q1i);
                            qelem(l2, k, l, q2r, q2i);
                            qelem(l3, n, m, q3r, q3i);
                            q3i = -q3i;
                            double ar = q1r * q2r - q1i * q2i;
                            double ai = q1r * q2i + q1i * q2r;
                            sre += (ar * q3r - ai * q3i) * cg;
                        }
                vals[(j * d2 + l) * d3 + m] = sre;
                n2 += sre * sre;
            }
    double inv = 1.0 / sqrt(n2);
    for (int t = 0; t < d1 * d2 * d3; ++t)
        g_w3j[W3OFF[p] + t] = (float)(vals[t] * inv);
}

// ---------------- zero / count / divide ----------------
__global__ void k_zero(float* __restrict__ out) {
    int i = blockIdx.x * blockDim.x + threadIdx.x;
    if (i < NN * 144) out[i] = 0.0f;
    if (i < NN) g_cnt[i] = 0.0f;
}

__global__ void k_count(const int* __restrict__ edst) {
    int i = blockIdx.x * blockDim.x + threadIdx.x;
    if (i < NE) atomicAdd(&g_cnt[edst[i]], 1.0f);
}

__global__ void k_div(float* __restrict__ out) {
    int i = blockIdx.x * blockDim.x + threadIdx.x;
    if (i < NN * 144) {
        float c = g_cnt[i / 144];
        out[i] = out[i] / fmaxf(c, 1.0f);
    }
}

// ---------------- kernel A: geometry + radial + MLP(8->64->64->64) ----------------
__global__ void __launch_bounds__(256) k_edge_mlp(
    const float* __restrict__ pos, const int* __restrict__ batch,
    const int* __restrict__ esrc, const int* __restrict__ edst,
    const float* __restrict__ eshift, const float* __restrict__ cell,
    const float* __restrict__ w0, const float* __restrict__ b0,
    const float* __restrict__ w1, const float* __restrict__ b1,
    const float* __restrict__ w2, const float* __restrict__ b2)
{
    __shared__ float s_sh[4][9];
    __shared__ float s_emb[4][8];
    __shared__ float s_h[4][2][64];
    const int g = threadIdx.x >> 6;
    const int t = threadIdx.x & 63;
    const int e = blockIdx.x * 4 + g;

    if (t == 0) {
        const int src = esrc[e], dst = edst[e];
        const int b = batch[src];
        const float s0 = eshift[e * 3 + 0], s1 = eshift[e * 3 + 1], s2 = eshift[e * 3 + 2];
        const float* C = cell + b * 9;
        float vx = pos[dst * 3 + 0] - pos[src * 3 + 0] + s0 * C[0] + s1 * C[3] + s2 * C[6];
        float vy = pos[dst * 3 + 1] - pos[src * 3 + 1] + s0 * C[1] + s1 * C[4] + s2 * C[7];
        float vz = pos[dst * 3 + 2] - pos[src * 3 + 2] + s0 * C[2] + s1 * C[5] + s2 * C[8];
        float r = sqrtf(vx * vx + vy * vy + vz * vz + 1e-12f);
        float ir = 1.0f / r;
        float x = vx * ir, y = vy * ir, z = vz * ir;
        const float s3c = 1.7320508075688772f;
        const float s15 = 3.8729833462074170f;
        const float s5  = 2.2360679774997896f;
        s_sh[g][0] = 1.0f;
        s_sh[g][1] = s3c * y;
        s_sh[g][2] = s3c * z;
        s_sh[g][3] = s3c * x;
        s_sh[g][4] = s15 * x * y;
        s_sh[g][5] = s15 * y * z;
        s_sh[g][6] = 0.5f * s5 * (3.0f * z * z - 1.0f);
        s_sh[g][7] = s15 * x * z;
        s_sh[g][8] = 0.5f * s15 * (x * x - y * y);
        float xr = fminf(fmaxf(r * (1.0f / 6.0f), 0.0f), 1.0f);
        float gate = (r <= 6.0f) ? 2.8284271247461903f : 0.0f;
        #pragma unroll
        for (int jb = 0; jb < 8; ++jb) {
            float d = (xr - (float)jb * (1.0f / 7.0f)) * 7.0f;
            s_emb[g][jb] = expf(-0.5f * d * d) * gate;
        }
    }
    __syncthreads();

    float a = b0[t];
    #pragma unroll
    for (int c = 0; c < 8; ++c) a += s_emb[g][c] * w0[c * 64 + t];
    a = a / (1.0f + expf(-a));
    s_h[g][0][t] = a;
    __syncthreads();

    a = b1[t];
    #pragma unroll 8
    for (int c = 0; c < 64; ++c) a += s_h[g][0][c] * w1[c * 64 + t];
    a = a / (1.0f + expf(-a));
    s_h[g][1][t] = a;
    __syncthreads();

    a = b2[t];
    #pragma unroll 8
    for (int c = 0; c < 64; ++c) a += s_h[g][1][c] * w2[c * 64 + t];
    a = a / (1.0f + expf(-a));
    g_H[(size_t)t * NE + e] = a;                    // TRANSPOSED store [k][e]
    if (t < 9) g_sh[(size_t)e * 9 + t] = s_sh[g][t];
}

// ---------------- kernel B1: SGEMM  Wv[128e x 2816] = H @ w3 + b3  (f32x2) ----------------
// grid (22, chunk_blocks), block 256, dynamic smem 64KB.
__global__ void __launch_bounds__(256) k_gemm(
    const float* __restrict__ w3, const float* __restrict__ b3, int e_base)
{
    extern __shared__ float smem[];
    float* sA = smem;              // [64][128]  H^T tile
    float* sB = smem + 64 * 128;   // [64][128]  w3 tile

    const int t  = threadIdx.x;
    const int n0 = blockIdx.x * 128;
    const int e0 = e_base + blockIdx.y * 128;

    #pragma unroll
    for (int i = 0; i < 8; ++i) {
        int lin = t + i * 256;                  // 0..2047
        int k = lin >> 5, q = lin & 31;
        float4 va = *reinterpret_cast<const float4*>(&g_H[(size_t)k * NE + e0 + q * 4]);
        *reinterpret_cast<float4*>(&sA[k * 128 + q * 4]) = va;
        float4 vb = __ldg(reinterpret_cast<const float4*>(&w3[(size_t)k * 2816 + n0 + q * 4]));
        *reinterpret_cast<float4*>(&sB[k * 128 + q * 4]) = vb;
    }
    __syncthreads();

    const int tx = t & 15, ty = t >> 4;
    unsigned long long acc[8][4];
    {
        float4 bb0 = __ldg(reinterpret_cast<const float4*>(&b3[n0 + tx * 8]));
        float4 bb1 = __ldg(reinterpret_cast<const float4*>(&b3[n0 + tx * 8 + 4]));
        unsigned long long i0 = pk2(bb0.x, bb0.y), i1 = pk2(bb0.z, bb0.w);
        unsigned long long i2 = pk2(bb1.x, bb1.y), i3 = pk2(bb1.z, bb1.w);
        #pragma unroll
        for (int m = 0; m < 8; ++m) { acc[m][0] = i0; acc[m][1] = i1; acc[m][2] = i2; acc[m][3] = i3; }
    }

    #pragma unroll 4
    for (int k = 0; k < 64; ++k) {
        float4 a0 = *reinterpret_cast<const float4*>(&sA[k * 128 + ty * 8]);
        float4 a1 = *reinterpret_cast<const float4*>(&sA[k * 128 + ty * 8 + 4]);
        float4 b0 = *reinterpret_cast<const float4*>(&sB[k * 128 + tx * 8]);
        float4 b1 = *reinterpret_cast<const float4*>(&sB[k * 128 + tx * 8 + 4]);
        unsigned long long bp0 = pk2(b0.x, b0.y), bp1 = pk2(b0.z, b0.w);
        unsigned long long bp2 = pk2(b1.x, b1.y), bp3 = pk2(b1.z, b1.w);
        float am[8] = {a0.x, a0.y, a0.z, a0.w, a1.x, a1.y, a1.z, a1.w};
        #pragma unroll
        for (int m = 0; m < 8; ++m) {
            unsigned long long ad = pk2(am[m], am[m]);
            fma2(acc[m][0], ad, bp0);
            fma2(acc[m][1], ad, bp1);
            fma2(acc[m][2], ad, bp2);
            fma2(acc[m][3], ad, bp3);
        }
    }

    #pragma unroll
    for (int m = 0; m < 8; ++m) {
        float2 r0 = up2(acc[m][0]), r1 = up2(acc[m][1]);
        float2 r2 = up2(acc[m][2]), r3 = up2(acc[m][3]);
        size_t row = (size_t)(blockIdx.y * 128 + ty * 8 + m) * 2816 + n0 + tx * 8;
        *reinterpret_cast<float4*>(&g_Wv[row])     = make_float4(r0.x, r0.y, r1.x, r1.y);
        *reinterpret_cast<float4*>(&g_Wv[row + 4]) = make_float4(r2.x, r2.y, r3.x, r3.y);
    }
}

// ---------------- kernel B2: T-contraction + scatter ----------------
// Block = 256 threads, 16 edges. Phase B: tid = e*16 + uh*4 + wq.
__global__ void __launch_bounds__(256) k_tp2(
    const float* __restrict__ f_in,
    const int* __restrict__ esrc, const int* __restrict__ edst,
    float* __restrict__ out, int e_base)
{
    __shared__ float sT[16][560];
    __shared__ float ssh[16][9];
    __shared__ int   ssrc[16];
    __shared__ int   sdst[16];

    const int tid = threadIdx.x;
    const int e0  = e_base + (blockIdx.x << 4);

    if (tid < 144) ssh[tid / 9][tid % 9] = g_sh[(size_t)e0 * 9 + tid];
    if (tid < 16) ssrc[tid] = esrc[e0 + tid];
    else if (tid < 32) sdst[tid - 16] = edst[e0 + tid - 16];
    __syncthreads();

    // ---- phase A: T[e,u,(p,k)] = alpha * sum_{i,j} x1[e,i,u]*sh[e,j]*W3J[i,j,k]
    {
        const int e = tid >> 4, u = tid & 15;
        const float* x1 = f_in + (size_t)ssrc[e] * 144;
        float xall[9];
        xall[0] = x1[u];
        #pragma unroll
        for (int i = 0; i < 3; ++i) xall[1 + i] = x1[16 + i * 16 + u];
        #pragma unroll
        for (int i = 0; i < 5; ++i) xall[4 + i] = x1[64 + i * 16 + u];
        float sl[9];
        #pragma unroll
        for (int j = 0; j < 9; ++j) sl[j] = ssh[e][j];
        float* Te = sT[e];
        #pragma unroll
        for (int p = 0; p < 11; ++p) {
            const int l1 = PL1[p], l2 = PL2[p];
            const int d1 = 2 * l1 + 1, d2 = 2 * l2 + 1, d3 = PD3[p];
            float acc[5];
            #pragma unroll
            for (int k = 0; k < 5; ++k) acc[k] = 0.0f;
            const float* wj = g_w3j + W3OFF[p];
            #pragma unroll
            for (int i = 0; i < d1; ++i) {
                const float xi = xall[XO[l1] + i];
                #pragma unroll
                for (int j = 0; j < d2; ++j) {
                    const float xs = xi * sl[XO[l2] + j];
                    #pragma unroll
                    for (int k = 0; k < d3; ++k)
                        acc[k] += xs * __ldg(&wj[(i * d2 + j) * d3 + k]);
                }
            }
            #pragma unroll
            for (int k = 0; k < d3; ++k)
                Te[TOFF[p] + u * d3 + k] = ALPHA[p] * acc[k];
        }
    }
    __syncthreads();

    // ---- phase B: msg[e,row,w] = sum_{p,u} T[e,p,u,row] * Wv[e, p*256+u*16+w]
    const int e  = tid >> 4;
    const int uh = (tid >> 2) & 3;
    const int wq = tid & 3;
    float4 acc[9];
    #pragma unroll
    for (int a = 0; a < 9; ++a) acc[a] = make_float4(0.f, 0.f, 0.f, 0.f);

    const float4* wv = reinterpret_cast<const float4*>(
        g_Wv + (size_t)((blockIdx.x << 4) + e) * 2816) + wq;
    const float* Te = sT[e];

    #pragma unroll
    for (int p = 0; p < 11; ++p) {
        const int d3 = PD3[p];
        #pragma unroll
        for (int ui = 0; ui < 4; ++ui) {
            const int u = uh * 4 + ui;
            float4 v = __ldg(&wv[(p * 16 + u) * 4]);
            #pragma unroll
            for (int k = 0; k < d3; ++k) {
                const float tv = Te[TOFF[p] + u * d3 + k];
                const int a = AROW[p] + k;
                acc[a].x += tv * v.x; acc[a].y += tv * v.y;
                acc[a].z += tv * v.z; acc[a].w += tv * v.w;
            }
        }
    }

    #pragma unroll
    for (int a = 0; a < 9; ++a) {
        #pragma unroll
        for (int off = 4; off <= 8; off <<= 1) {
            acc[a].x += __shfl_xor_sync(0xffffffffu, acc[a].x, off);
            acc[a].y += __shfl_xor_sync(0xffffffffu, acc[a].y, off);
            acc[a].z += __shfl_xor_sync(0xffffffffu, acc[a].z, off);
            acc[a].w += __shfl_xor_sync(0xffffffffu, acc[a].w, off);
        }
    }
    if (uh == 0) {
        float* op = out + (size_t)sdst[e] * 144 + (wq << 2);
        #pragma unroll
        for (int a = 0; a < 9; ++a) {
            atomicAdd(op + a * 16 + 0, acc[a].x);
            atomicAdd(op + a * 16 + 1, acc[a].y);
            atomicAdd(op + a * 16 + 2, acc[a].z);
            atomicAdd(op + a * 16 + 3, acc[a].w);
        }
    }
}

// ---------------- launch ----------------
extern "C" void kernel_launch(void* const* d_in, const int* in_sizes, int n_in,
                              void* d_out, int out_size)
{
    const float* f_in   = (const float*)d_in[0];
    const float* pos    = (const float*)d_in[1];
    const int*   batch  = (const int*)d_in[3];
    const int*   esrc   = (const int*)d_in[4];
    const int*   edst   = (const int*)d_in[5];
    const float* eshift = (const float*)d_in[6];
    const float* cell   = (const float*)d_in[7];
    const float* w0 = (const float*)d_in[8];
    const float* b0 = (const float*)d_in[9];
    const float* w1 = (const float*)d_in[10];
    const float* b1 = (const float*)d_in[11];
    const float* w2 = (const float*)d_in[12];
    const float* b2 = (const float*)d_in[13];
    const float* w3 = (const float*)d_in[14];
    const float* b3 = (const float*)d_in[15];
    float* out = (float*)d_out;

    static bool attr_set = false;
    if (!attr_set) {
        cudaFuncSetAttribute(k_gemm, cudaFuncAttributeMaxDynamicSharedMemorySize, 65536);
        attr_set = true;
    }

    k_init_w3j<<<1, 32>>>();
    k_zero<<<(NN * 144 + 255) / 256, 256>>>(out);
    k_edge_mlp<<<NE / 4, 256>>>(pos, batch, esrc, edst, eshift, cell,
                                w0, b0, w1, b1, w2, b2);
    k_count<<<(NE + 255) / 256, 256>>>(edst);

    for (int c = 0; c < NCHUNK; ++c) {
        const int e_base = c * CH_E;
        k_gemm<<<dim3(22, CH_E / 128), 256, 65536>>>(w3, b3, e_base);
        k_tp2<<<CH_E / 16, 256>>>(f_in, esrc, edst, out, e_base);
    }

    k_div<<<(NN * 144 + 255) / 256, 256>>>(out);
}

// round 4
// speedup vs baseline: 5.1371x; 4.1624x over previous
#include <cuda_runtime.h>
#include <math.h>

#define NE 160000
#define NN 10000
#define CH_E 32000           // edges per Wv chunk (5 chunks)
#define NCHUNK 5

// ---------------- device scratch ----------------
__device__ float g_H[64 * NE];               // MLP hidden, TRANSPOSED: [k][e]
__device__ float g_sh[NE * 9];               // spherical harmonics
__device__ float g_cnt[NN];                  // per-node edge counts
__device__ float g_w3j[363];                 // Wigner-3j tables
__device__ float g_Wv[(size_t)CH_E * 2816];  // chunk of per-edge weights

// ---------------- path metadata ----------------
__device__ constexpr int PL1[11]   = {0,0,0,1,1,1,1,2,2,2,2};
__device__ constexpr int PL2[11]   = {0,1,2,0,1,1,2,0,1,2,2};
__device__ constexpr int PL3[11]   = {0,1,2,1,0,2,1,2,1,0,2};
__device__ constexpr int PD3[11]   = {1,3,5,3,1,5,3,5,3,1,5};
__device__ constexpr int W3OFF[11] = {0,1,10,35,44,53,98,143,168,213,238};
__device__ constexpr int TOFF[11]  = {0,16,64,144,192,208,288,336,416,464,480};
__device__ constexpr int AROW[11]  = {0,1,4,1,0,4,1,4,1,0,4};
__device__ constexpr float ALPHA[11] = {
    0.14433756729740643f, 0.21650635094610965f, 0.27950849718747373f,
    0.21650635094610965f, 0.14433756729740643f, 0.27950849718747373f,
    0.21650635094610965f, 0.27950849718747373f, 0.21650635094610965f,
    0.14433756729740643f, 0.27950849718747373f};
__device__ constexpr int XO[3] = {0,1,4};

// ---------------- f32x2 packed FMA helpers ----------------
__device__ __forceinline__ unsigned long long pk2(float x, float y) {
    unsigned long long r;
    asm("mov.b64 %0, {%1,%2};" : "=l"(r) : "f"(x), "f"(y));
    return r;
}
__device__ __forceinline__ void fma2(unsigned long long& d, unsigned long long a, unsigned long long b) {
    asm("fma.rn.f32x2 %0, %1, %2, %0;" : "+l"(d) : "l"(a), "l"(b));
}
__device__ __forceinline__ float2 up2(unsigned long long v) {
    float2 r;
    asm("mov.b64 {%0,%1}, %2;" : "=f"(r.x), "=f"(r.y) : "l"(v));
    return r;
}

// ---------------- W3J init (exact FP64 replica, PARALLELIZED) ----------------
__device__ double dfact(int n) { double r = 1.0; for (int i = 2; i <= n; ++i) r *= (double)i; return r; }

__device__ double su2_cg(int j1, int m1, int j2, int m2, int j3, int m3) {
    if (m1 + m2 != m3) return 0.0;
    int vmin = 0;
    if (-j1 + j2 + m3 > vmin) vmin = -j1 + j2 + m3;
    if (-j1 + m1 > vmin)      vmin = -j1 + m1;
    int vmax = j2 + j3 + m1;
    if (j3 - j1 + j2 < vmax) vmax = j3 - j1 + j2;
    if (j3 + m3 < vmax)      vmax = j3 + m3;
    double C = sqrt((2.0 * j3 + 1.0) * dfact(j3 + j1 - j2) * dfact(j3 - j1 + j2) * dfact(j1 + j2 - j3)
                    / dfact(j1 + j2 + j3 + 1)
                    * dfact(j3 + m3) * dfact(j3 - m3)
                    / (dfact(j1 - m1) * dfact(j1 + m1) * dfact(j2 - m2) * dfact(j2 + m2)));
    double S = 0.0;
    for (int v = vmin; v <= vmax; ++v) {
        double sgn = ((v + j2 + m2) & 1) ? -1.0 : 1.0;
        S += sgn / dfact(v) * dfact(j2 + j3 + m1 - v) * dfact(j1 - m1 + v)
             / dfact(j3 - j1 + j2 - v) / dfact(j3 + m3 - v) / dfact(v + j1 - j2 - m3);
    }
    return C * S;
}

__device__ void qelem(int l, int r, int c, double& re, double& im) {
    int m = r - l;
    double vr = 0.0, vi = 0.0;
    const double is2 = 0.70710678118654752440;
    if (m < 0) {
        if (c == l - m) vr = is2;
        if (c == l + m) vi = -is2;
    } else if (m == 0) {
        if (c == l) vr = 1.0;
    } else {
        double sg = (m & 1) ? -1.0 : 1.0;
        if (c == l + m) vr = sg * is2;
        if (c == l - m) vi = sg * is2;
    }
    if (l == 1) { double t = vr; vr = vi; vi = -t; }
    else if (l == 2) { vr = -vr; vi = -vi; }
    re = vr; im = vi;
}

// One block per path, one thread per output element (j,l,m).
__global__ void k_init_w3j() {
    __shared__ double s_val[125];
    __shared__ double s_inv;
    const int p = blockIdx.x;
    const int l1 = PL1[p], l2 = PL2[p], l3 = PL3[p];
    const int d1 = 2 * l1 + 1, d2 = 2 * l2 + 1, d3 = 2 * l3 + 1;
    const int nel = d1 * d2 * d3;
    const int t = threadIdx.x;

    if (t < nel) {
        const int j = t / (d2 * d3);
        const int l = (t / d3) % d2;
        const int m = t % d3;
        double sre = 0.0;
        for (int i = 0; i < d1; ++i)
            for (int k = 0; k < d2; ++k) {
                // m3 = m1+m2 forces n; other n give cg = 0
                const int n = (i - l1) + (k - l2) + l3;
                if (n < 0 || n >= d3) continue;
                const double cg = su2_cg(l1, i - l1, l2, k - l2, l3, n - l3);
                if (cg == 0.0) continue;
                double q1r, q1i, q2r, q2i, q3r, q3i;
                qelem(l1, i, j, q1r, q1i);
                qelem(l2, k, l, q2r, q2i);
                qelem(l3, n, m, q3r, q3i);
                q3i = -q3i; // conj(q(l3).T)[m,n] = conj(q(l3)[n,m])
                const double ar = q1r * q2r - q1i * q2i;
                const double ai = q1r * q2i + q1i * q2r;
                sre += (ar * q3r - ai * q3i) * cg;
            }
        s_val[t] = sre;
    }
    __syncthreads();
    if (t == 0) {
        double n2 = 0.0;
        for (int q = 0; q < nel; ++q) n2 += s_val[q] * s_val[q];
        s_inv = 1.0 / sqrt(n2);
    }
    __syncthreads();
    if (t < nel)
        g_w3j[W3OFF[p] + t] = (float)(s_val[t] * s_inv);
}

// ---------------- zero / count / divide ----------------
__global__ void k_zero(float* __restrict__ out) {
    int i = blockIdx.x * blockDim.x + threadIdx.x;
    if (i < NN * 144) out[i] = 0.0f;
    if (i < NN) g_cnt[i] = 0.0f;
}

__global__ void k_count(const int* __restrict__ edst) {
    int i = blockIdx.x * blockDim.x + threadIdx.x;
    if (i < NE) atomicAdd(&g_cnt[edst[i]], 1.0f);
}

__global__ void k_div(float* __restrict__ out) {
    int i = blockIdx.x * blockDim.x + threadIdx.x;
    if (i < NN * 144) {
        float c = g_cnt[i / 144];
        out[i] = out[i] / fmaxf(c, 1.0f);
    }
}

// ---------------- kernel A: geometry + radial + MLP(8->64->64->64) ----------------
__global__ void __launch_bounds__(256) k_edge_mlp(
    const float* __restrict__ pos, const int* __restrict__ batch,
    const int* __restrict__ esrc, const int* __restrict__ edst,
    const float* __restrict__ eshift, const float* __restrict__ cell,
    const float* __restrict__ w0, const float* __restrict__ b0,
    const float* __restrict__ w1, const float* __restrict__ b1,
    const float* __restrict__ w2, const float* __restrict__ b2)
{
    __shared__ float s_sh[4][9];
    __shared__ float s_emb[4][8];
    __shared__ float s_h[4][2][64];
    const int g = threadIdx.x >> 6;
    const int t = threadIdx.x & 63;
    const int e = blockIdx.x * 4 + g;

    if (t == 0) {
        const int src = esrc[e], dst = edst[e];
        const int b = batch[src];
        const float s0 = eshift[e * 3 + 0], s1 = eshift[e * 3 + 1], s2 = eshift[e * 3 + 2];
        const float* C = cell + b * 9;
        float vx = pos[dst * 3 + 0] - pos[src * 3 + 0] + s0 * C[0] + s1 * C[3] + s2 * C[6];
        float vy = pos[dst * 3 + 1] - pos[src * 3 + 1] + s0 * C[1] + s1 * C[4] + s2 * C[7];
        float vz = pos[dst * 3 + 2] - pos[src * 3 + 2] + s0 * C[2] + s1 * C[5] + s2 * C[8];
        float r = sqrtf(vx * vx + vy * vy + vz * vz + 1e-12f);
        float ir = 1.0f / r;
        float x = vx * ir, y = vy * ir, z = vz * ir;
        const float s3c = 1.7320508075688772f;
        const float s15 = 3.8729833462074170f;
        const float s5  = 2.2360679774997896f;
        s_sh[g][0] = 1.0f;
        s_sh[g][1] = s3c * y;
        s_sh[g][2] = s3c * z;
        s_sh[g][3] = s3c * x;
        s_sh[g][4] = s15 * x * y;
        s_sh[g][5] = s15 * y * z;
        s_sh[g][6] = 0.5f * s5 * (3.0f * z * z - 1.0f);
        s_sh[g][7] = s15 * x * z;
        s_sh[g][8] = 0.5f * s15 * (x * x - y * y);
        float xr = fminf(fmaxf(r * (1.0f / 6.0f), 0.0f), 1.0f);
        float gate = (r <= 6.0f) ? 2.8284271247461903f : 0.0f;
        #pragma unroll
        for (int jb = 0; jb < 8; ++jb) {
            float d = (xr - (float)jb * (1.0f / 7.0f)) * 7.0f;
            s_emb[g][jb] = expf(-0.5f * d * d) * gate;
        }
    }
    __syncthreads();

    float a = b0[t];
    #pragma unroll
    for (int c = 0; c < 8; ++c) a += s_emb[g][c] * w0[c * 64 + t];
    a = a / (1.0f + expf(-a));
    s_h[g][0][t] = a;
    __syncthreads();

    a = b1[t];
    #pragma unroll 8
    for (int c = 0; c < 64; ++c) a += s_h[g][0][c] * w1[c * 64 + t];
    a = a / (1.0f + expf(-a));
    s_h[g][1][t] = a;
    __syncthreads();

    a = b2[t];
    #pragma unroll 8
    for (int c = 0; c < 64; ++c) a += s_h[g][1][c] * w2[c * 64 + t];
    a = a / (1.0f + expf(-a));
    g_H[(size_t)t * NE + e] = a;                    // TRANSPOSED store [k][e]
    if (t < 9) g_sh[(size_t)e * 9 + t] = s_sh[g][t];
}

// ---------------- kernel B1: SGEMM  Wv[128e x 2816] = H @ w3 + b3  (f32x2) ----------------
__global__ void __launch_bounds__(256) k_gemm(
    const float* __restrict__ w3, const float* __restrict__ b3, int e_base)
{
    extern __shared__ float smem[];
    float* sA = smem;              // [64][128]  H^T tile
    float* sB = smem + 64 * 128;   // [64][128]  w3 tile

    const int t  = threadIdx.x;
    const int n0 = blockIdx.x * 128;
    const int e0 = e_base + blockIdx.y * 128;

    #pragma unroll
    for (int i = 0; i < 8; ++i) {
        int lin = t + i * 256;                  // 0..2047
        int k = lin >> 5, q = lin & 31;
        float4 va = *reinterpret_cast<const float4*>(&g_H[(size_t)k * NE + e0 + q * 4]);
        *reinterpret_cast<float4*>(&sA[k * 128 + q * 4]) = va;
        float4 vb = __ldg(reinterpret_cast<const float4*>(&w3[(size_t)k * 2816 + n0 + q * 4]));
        *reinterpret_cast<float4*>(&sB[k * 128 + q * 4]) = vb;
    }
    __syncthreads();

    const int tx = t & 15, ty = t >> 4;
    unsigned long long acc[8][4];
    {
        float4 bb0 = __ldg(reinterpret_cast<const float4*>(&b3[n0 + tx * 8]));
        float4 bb1 = __ldg(reinterpret_cast<const float4*>(&b3[n0 + tx * 8 + 4]));
        unsigned long long i0 = pk2(bb0.x, bb0.y), i1 = pk2(bb0.z, bb0.w);
        unsigned long long i2 = pk2(bb1.x, bb1.y), i3 = pk2(bb1.z, bb1.w);
        #pragma unroll
        for (int m = 0; m < 8; ++m) { acc[m][0] = i0; acc[m][1] = i1; acc[m][2] = i2; acc[m][3] = i3; }
    }

    #pragma unroll 4
    for (int k = 0; k < 64; ++k) {
        float4 a0 = *reinterpret_cast<const float4*>(&sA[k * 128 + ty * 8]);
        float4 a1 = *reinterpret_cast<const float4*>(&sA[k * 128 + ty * 8 + 4]);
        float4 b0 = *reinterpret_cast<const float4*>(&sB[k * 128 + tx * 8]);
        float4 b1 = *reinterpret_cast<const float4*>(&sB[k * 128 + tx * 8 + 4]);
        unsigned long long bp0 = pk2(b0.x, b0.y), bp1 = pk2(b0.z, b0.w);
        unsigned long long bp2 = pk2(b1.x, b1.y), bp3 = pk2(b1.z, b1.w);
        float am[8] = {a0.x, a0.y, a0.z, a0.w, a1.x, a1.y, a1.z, a1.w};
        #pragma unroll
        for (int m = 0; m < 8; ++m) {
            unsigned long long ad = pk2(am[m], am[m]);
            fma2(acc[m][0], ad, bp0);
            fma2(acc[m][1], ad, bp1);
            fma2(acc[m][2], ad, bp2);
            fma2(acc[m][3], ad, bp3);
        }
    }

    #pragma unroll
    for (int m = 0; m < 8; ++m) {
        float2 r0 = up2(acc[m][0]), r1 = up2(acc[m][1]);
        float2 r2 = up2(acc[m][2]), r3 = up2(acc[m][3]);
        size_t row = (size_t)(blockIdx.y * 128 + ty * 8 + m) * 2816 + n0 + tx * 8;
        *reinterpret_cast<float4*>(&g_Wv[row])     = make_float4(r0.x, r0.y, r1.x, r1.y);
        *reinterpret_cast<float4*>(&g_Wv[row + 4]) = make_float4(r2.x, r2.y, r3.x, r3.y);
    }
}

// ---------------- kernel B2: T-contraction + scatter ----------------
__global__ void __launch_bounds__(256) k_tp2(
    const float* __restrict__ f_in,
    const int* __restrict__ esrc, const int* __restrict__ edst,
    float* __restrict__ out, int e_base)
{
    __shared__ float sT[16][560];
    __shared__ float ssh[16][9];
    __shared__ int   ssrc[16];
    __shared__ int   sdst[16];

    const int tid = threadIdx.x;
    const int e0  = e_base + (blockIdx.x << 4);

    if (tid < 144) ssh[tid / 9][tid % 9] = g_sh[(size_t)e0 * 9 + tid];
    if (tid < 16) ssrc[tid] = esrc[e0 + tid];
    else if (tid < 32) sdst[tid - 16] = edst[e0 + tid - 16];
    __syncthreads();

    // ---- phase A: T[e,u,(p,k)] = alpha * sum_{i,j} x1[e,i,u]*sh[e,j]*W3J[i,j,k]
    {
        const int e = tid >> 4, u = tid & 15;
        const float* x1 = f_in + (size_t)ssrc[e] * 144;
        float xall[9];
        xall[0] = x1[u];
        #pragma unroll
        for (int i = 0; i < 3; ++i) xall[1 + i] = x1[16 + i * 16 + u];
        #pragma unroll
        for (int i = 0; i < 5; ++i) xall[4 + i] = x1[64 + i * 16 + u];
        float sl[9];
        #pragma unroll
        for (int j = 0; j < 9; ++j) sl[j] = ssh[e][j];
        float* Te = sT[e];
        #pragma unroll
        for (int p = 0; p < 11; ++p) {
            const int l1 = PL1[p], l2 = PL2[p];
            const int d1 = 2 * l1 + 1, d2 = 2 * l2 + 1, d3 = PD3[p];
            float acc[5];
            #pragma unroll
            for (int k = 0; k < 5; ++k) acc[k] = 0.0f;
            const float* wj = g_w3j + W3OFF[p];
            #pragma unroll
            for (int i = 0; i < d1; ++i) {
                const float xi = xall[XO[l1] + i];
                #pragma unroll
                for (int j = 0; j < d2; ++j) {
                    const float xs = xi * sl[XO[l2] + j];
                    #pragma unroll
                    for (int k = 0; k < d3; ++k)
                        acc[k] += xs * __ldg(&wj[(i * d2 + j) * d3 + k]);
                }
            }
            #pragma unroll
            for (int k = 0; k < d3; ++k)
                Te[TOFF[p] + u * d3 + k] = ALPHA[p] * acc[k];
        }
    }
    __syncthreads();

    // ---- phase B: msg[e,row,w] = sum_{p,u} T[e,p,u,row] * Wv[e, p*256+u*16+w]
    const int e  = tid >> 4;
    const int uh = (tid >> 2) & 3;
    const int wq = tid & 3;
    float4 acc[9];
    #pragma unroll
    for (int a = 0; a < 9; ++a) acc[a] = make_float4(0.f, 0.f, 0.f, 0.f);

    const float4* wv = reinterpret_cast<const float4*>(
        g_Wv + (size_t)((blockIdx.x << 4) + e) * 2816) + wq;
    const float* Te = sT[e];

    #pragma unroll
    for (int p = 0; p < 11; ++p) {
        const int d3 = PD3[p];
        #pragma unroll
        for (int ui = 0; ui < 4; ++ui) {
            const int u = uh * 4 + ui;
            float4 v = __ldg(&wv[(p * 16 + u) * 4]);
            #pragma unroll
            for (int k = 0; k < d3; ++k) {
                const float tv = Te[TOFF[p] + u * d3 + k];
                const int a = AROW[p] + k;
                acc[a].x += tv * v.x; acc[a].y += tv * v.y;
                acc[a].z += tv * v.z; acc[a].w += tv * v.w;
            }
        }
    }

    #pragma unroll
    for (int a = 0; a < 9; ++a) {
        #pragma unroll
        for (int off = 4; off <= 8; off <<= 1) {
            acc[a].x += __shfl_xor_sync(0xffffffffu, acc[a].x, off);
            acc[a].y += __shfl_xor_sync(0xffffffffu, acc[a].y, off);
            acc[a].z += __shfl_xor_sync(0xffffffffu, acc[a].z, off);
            acc[a].w += __shfl_xor_sync(0xffffffffu, acc[a].w, off);
        }
    }
    if (uh == 0) {
        float* op = out + (size_t)sdst[e] * 144 + (wq << 2);
        #pragma unroll
        for (int a = 0; a < 9; ++a) {
            atomicAdd(op + a * 16 + 0, acc[a].x);
            atomicAdd(op + a * 16 + 1, acc[a].y);
            atomicAdd(op + a * 16 + 2, acc[a].z);
            atomicAdd(op + a * 16 + 3, acc[a].w);
        }
    }
}

// ---------------- launch ----------------
extern "C" void kernel_launch(void* const* d_in, const int* in_sizes, int n_in,
                              void* d_out, int out_size)
{
    const float* f_in   = (const float*)d_in[0];
    const float* pos    = (const float*)d_in[1];
    const int*   batch  = (const int*)d_in[3];
    const int*   esrc   = (const int*)d_in[4];
    const int*   edst   = (const int*)d_in[5];
    const float* eshift = (const float*)d_in[6];
    const float* cell   = (const float*)d_in[7];
    const float* w0 = (const float*)d_in[8];
    const float* b0 = (const float*)d_in[9];
    const float* w1 = (const float*)d_in[10];
    const float* b1 = (const float*)d_in[11];
    const float* w2 = (const float*)d_in[12];
    const float* b2 = (const float*)d_in[13];
    const float* w3 = (const float*)d_in[14];
    const float* b3 = (const float*)d_in[15];
    float* out = (float*)d_out;

    static bool attr_set = false;
    if (!attr_set) {
        cudaFuncSetAttribute(k_gemm, cudaFuncAttributeMaxDynamicSharedMemorySize, 65536);
        attr_set = true;
    }

    k_init_w3j<<<11, 128>>>();
    k_zero<<<(NN * 144 + 255) / 256, 256>>>(out);
    k_edge_mlp<<<NE / 4, 256>>>(pos, batch, esrc, edst, eshift, cell,
                                w0, b0, w1, b1, w2, b2);
    k_count<<<(NE + 255) / 256, 256>>>(edst);

    for (int c = 0; c < NCHUNK; ++c) {
        const int e_base = c * CH_E;
        k_gemm<<<dim3(22, CH_E / 128), 256, 65536>>>(w3, b3, e_base);
        k_tp2<<<CH_E / 16, 256>>>(f_in, esrc, edst, out, e_base);
    }

    k_div<<<(NN * 144 + 255) / 256, 256>>>(out);
}

// round 6
// speedup vs baseline: 7.4919x; 1.4584x over previous
#include <cuda_runtime.h>
#include <cuda_bf16.h>
#include <math.h>
#include <cstdint>

#define NE 160000
#define NN 10000
#define CH_E 32000           // edges per Wv chunk (5 chunks)
#define NCHUNK 5

// ---------------- device scratch ----------------
__device__ __nv_bfloat16 g_Hhi[(size_t)NE * 64];     // MLP hidden, bf16 hi, [e][k]
__device__ __nv_bfloat16 g_Hlo[(size_t)NE * 64];     // MLP hidden, bf16 lo
__device__ __nv_bfloat16 g_w3Thi[(size_t)2816 * 64]; // w3 transposed [n][k], bf16 hi
__device__ __nv_bfloat16 g_w3Tlo[(size_t)2816 * 64]; // bf16 lo
__device__ float g_sh[NE * 9];               // spherical harmonics
__device__ float g_cnt[NN];                  // per-node edge counts
__device__ float g_w3j[363];                 // Wigner-3j tables
__device__ float g_Wv[(size_t)CH_E * 2816];  // chunk of per-edge weights

// ---------------- path metadata ----------------
__device__ constexpr int PL1[11]   = {0,0,0,1,1,1,1,2,2,2,2};
__device__ constexpr int PL2[11]   = {0,1,2,0,1,1,2,0,1,2,2};
__device__ constexpr int PL3[11]   = {0,1,2,1,0,2,1,2,1,0,2};
__device__ constexpr int PD3[11]   = {1,3,5,3,1,5,3,5,3,1,5};
__device__ constexpr int W3OFF[11] = {0,1,10,35,44,53,98,143,168,213,238};
__device__ constexpr int TOFF[11]  = {0,16,64,144,192,208,288,336,416,464,480};
__device__ constexpr int AROW[11]  = {0,1,4,1,0,4,1,4,1,0,4};
__device__ constexpr float ALPHA[11] = {
    0.14433756729740643f, 0.21650635094610965f, 0.27950849718747373f,
    0.21650635094610965f, 0.14433756729740643f, 0.27950849718747373f,
    0.21650635094610965f, 0.27950849718747373f, 0.21650635094610965f,
    0.14433756729740643f, 0.27950849718747373f};
__device__ constexpr int XO[3] = {0,1,4};

// ---------------- mma.sync m16n8k16 bf16 (valid on sm_100, no 'a' needed) ----------------
#define MMA_BF16(d, a, b) \
    asm volatile("mma.sync.aligned.m16n8k16.row.col.f32.bf16.bf16.f32 " \
        "{%0,%1,%2,%3}, {%4,%5,%6,%7}, {%8,%9}, {%0,%1,%2,%3};" \
        : "+f"((d)[0]), "+f"((d)[1]), "+f"((d)[2]), "+f"((d)[3]) \
        : "r"((a)[0]), "r"((a)[1]), "r"((a)[2]), "r"((a)[3]), \
          "r"((b)[0]), "r"((b)[1]))

// ---------------- W3J init (exact FP64 replica, parallelized) ----------------
__device__ double dfact(int n) { double r = 1.0; for (int i = 2; i <= n; ++i) r *= (double)i; return r; }

__device__ double su2_cg(int j1, int m1, int j2, int m2, int j3, int m3) {
    if (m1 + m2 != m3) return 0.0;
    int vmin = 0;
    if (-j1 + j2 + m3 > vmin) vmin = -j1 + j2 + m3;
    if (-j1 + m1 > vmin)      vmin = -j1 + m1;
    int vmax = j2 + j3 + m1;
    if (j3 - j1 + j2 < vmax) vmax = j3 - j1 + j2;
    if (j3 + m3 < vmax)      vmax = j3 + m3;
    double C = sqrt((2.0 * j3 + 1.0) * dfact(j3 + j1 - j2) * dfact(j3 - j1 + j2) * dfact(j1 + j2 - j3)
                    / dfact(j1 + j2 + j3 + 1)
                    * dfact(j3 + m3) * dfact(j3 - m3)
                    / (dfact(j1 - m1) * dfact(j1 + m1) * dfact(j2 - m2) * dfact(j2 + m2)));
    double S = 0.0;
    for (int v = vmin; v <= vmax; ++v) {
        double sgn = ((v + j2 + m2) & 1) ? -1.0 : 1.0;
        S += sgn / dfact(v) * dfact(j2 + j3 + m1 - v) * dfact(j1 - m1 + v)
             / dfact(j3 - j1 + j2 - v) / dfact(j3 + m3 - v) / dfact(v + j1 - j2 - m3);
    }
    return C * S;
}

__device__ void qelem(int l, int r, int c, double& re, double& im) {
    int m = r - l;
    double vr = 0.0, vi = 0.0;
    const double is2 = 0.70710678118654752440;
    if (m < 0) {
        if (c == l - m) vr = is2;
        if (c == l + m) vi = -is2;
    } else if (m == 0) {
        if (c == l) vr = 1.0;
    } else {
        double sg = (m & 1) ? -1.0 : 1.0;
        if (c == l + m) vr = sg * is2;
        if (c == l - m) vi = sg * is2;
    }
    if (l == 1) { double t = vr; vr = vi; vi = -t; }
    else if (l == 2) { vr = -vr; vi = -vi; }
    re = vr; im = vi;
}

__global__ void k_init_w3j() {
    __shared__ double s_val[125];
    __shared__ double s_inv;
    const int p = blockIdx.x;
    const int l1 = PL1[p], l2 = PL2[p], l3 = PL3[p];
    const int d1 = 2 * l1 + 1, d2 = 2 * l2 + 1, d3 = 2 * l3 + 1;
    const int nel = d1 * d2 * d3;
    const int t = threadIdx.x;

    if (t < nel) {
        const int j = t / (d2 * d3);
        const int l = (t / d3) % d2;
        const int m = t % d3;
        double sre = 0.0;
        for (int i = 0; i < d1; ++i)
            for (int k = 0; k < d2; ++k) {
                const int n = (i - l1) + (k - l2) + l3;
                if (n < 0 || n >= d3) continue;
                const double cg = su2_cg(l1, i - l1, l2, k - l2, l3, n - l3);
                if (cg == 0.0) continue;
                double q1r, q1i, q2r, q2i, q3r, q3i;
                qelem(l1, i, j, q1r, q1i);
                qelem(l2, k, l, q2r, q2i);
                qelem(l3, n, m, q3r, q3i);
                q3i = -q3i;
                const double ar = q1r * q2r - q1i * q2i;
                const double ai = q1r * q2i + q1i * q2r;
                sre += (ar * q3r - ai * q3i) * cg;
            }
        s_val[t] = sre;
    }
    __syncthreads();
    if (t == 0) {
        double n2 = 0.0;
        for (int q = 0; q < nel; ++q) n2 += s_val[q] * s_val[q];
        s_inv = 1.0 / sqrt(n2);
    }
    __syncthreads();
    if (t < nel)
        g_w3j[W3OFF[p] + t] = (float)(s_val[t] * s_inv);
}

// ---------------- zero / count / divide / w3 conversion ----------------
__global__ void k_zero(float* __restrict__ out) {
    int i = blockIdx.x * blockDim.x + threadIdx.x;
    if (i < NN * 144) out[i] = 0.0f;
    if (i < NN) g_cnt[i] = 0.0f;
}

__global__ void k_count(const int* __restrict__ edst) {
    int i = blockIdx.x * blockDim.x + threadIdx.x;
    if (i < NE) atomicAdd(&g_cnt[edst[i]], 1.0f);
}

__global__ void k_div(float* __restrict__ out) {
    int i = blockIdx.x * blockDim.x + threadIdx.x;
    if (i < NN * 144) {
        float c = g_cnt[i / 144];
        out[i] = out[i] / fmaxf(c, 1.0f);
    }
}

// w3 [64][2816] fp32 -> transposed [n][k] bf16 hi/lo
__global__ void k_conv_w3(const float* __restrict__ w3) {
    int i = blockIdx.x * blockDim.x + threadIdx.x;
    if (i >= 64 * 2816) return;
    int k = i / 2816, n = i % 2816;
    float v = w3[i];
    __nv_bfloat16 hi = __float2bfloat16(v);
    __nv_bfloat16 lo = __float2bfloat16(v - __bfloat162float(hi));
    g_w3Thi[(size_t)n * 64 + k] = hi;
    g_w3Tlo[(size_t)n * 64 + k] = lo;
}

// ---------------- kernel A: geometry + radial + MLP(8->64->64->64) ----------------
__global__ void __launch_bounds__(256) k_edge_mlp(
    const float* __restrict__ pos, const int* __restrict__ batch,
    const int* __restrict__ esrc, const int* __restrict__ edst,
    const float* __restrict__ eshift, const float* __restrict__ cell,
    const float* __restrict__ w0, const float* __restrict__ b0,
    const float* __restrict__ w1, const float* __restrict__ b1,
    const float* __restrict__ w2, const float* __restrict__ b2)
{
    __shared__ float s_sh[4][9];
    __shared__ float s_emb[4][8];
    __shared__ float s_h[4][2][64];
    const int g = threadIdx.x >> 6;
    const int t = threadIdx.x & 63;
    const int e = blockIdx.x * 4 + g;

    if (t == 0) {
        const int src = esrc[e], dst = edst[e];
        const int b = batch[src];
        const float s0 = eshift[e * 3 + 0], s1 = eshift[e * 3 + 1], s2 = eshift[e * 3 + 2];
        const float* C = cell + b * 9;
        float vx = pos[dst * 3 + 0] - pos[src * 3 + 0] + s0 * C[0] + s1 * C[3] + s2 * C[6];
        float vy = pos[dst * 3 + 1] - pos[src * 3 + 1] + s0 * C[1] + s1 * C[4] + s2 * C[7];
        float vz = pos[dst * 3 + 2] - pos[src * 3 + 2] + s0 * C[2] + s1 * C[5] + s2 * C[8];
        float r = sqrtf(vx * vx + vy * vy + vz * vz + 1e-12f);
        float ir = 1.0f / r;
        float x = vx * ir, y = vy * ir, z = vz * ir;
        const float s3c = 1.7320508075688772f;
        const float s15 = 3.8729833462074170f;
        const float s5  = 2.2360679774997896f;
        s_sh[g][0] = 1.0f;
        s_sh[g][1] = s3c * y;
        s_sh[g][2] = s3c * z;
        s_sh[g][3] = s3c * x;
        s_sh[g][4] = s15 * x * y;
        s_sh[g][5] = s15 * y * z;
        s_sh[g][6] = 0.5f * s5 * (3.0f * z * z - 1.0f);
        s_sh[g][7] = s15 * x * z;
        s_sh[g][8] = 0.5f * s15 * (x * x - y * y);
        float xr = fminf(fmaxf(r * (1.0f / 6.0f), 0.0f), 1.0f);
        float gate = (r <= 6.0f) ? 2.8284271247461903f : 0.0f;
        #pragma unroll
        for (int jb = 0; jb < 8; ++jb) {
            float d = (xr - (float)jb * (1.0f / 7.0f)) * 7.0f;
            s_emb[g][jb] = expf(-0.5f * d * d) * gate;
        }
    }
    __syncthreads();

    float a = b0[t];
    #pragma unroll
    for (int c = 0; c < 8; ++c) a += s_emb[g][c] * w0[c * 64 + t];
    a = a / (1.0f + expf(-a));
    s_h[g][0][t] = a;
    __syncthreads();

    a = b1[t];
    #pragma unroll 8
    for (int c = 0; c < 64; ++c) a += s_h[g][0][c] * w1[c * 64 + t];
    a = a / (1.0f + expf(-a));
    s_h[g][1][t] = a;
    __syncthreads();

    a = b2[t];
    #pragma unroll 8
    for (int c = 0; c < 64; ++c) a += s_h[g][1][c] * w2[c * 64 + t];
    a = a / (1.0f + expf(-a));
    __nv_bfloat16 hi = __float2bfloat16(a);
    __nv_bfloat16 lo = __float2bfloat16(a - __bfloat162float(hi));
    g_Hhi[(size_t)e * 64 + t] = hi;
    g_Hlo[(size_t)e * 64 + t] = lo;
    if (t < 9) g_sh[(size_t)e * 9 + t] = s_sh[g][t];
}

// ---------------- kernel B1: HMMA GEMM  Wv[128e x 128n] tiles, bf16 hi/lo 3-pass ----
// grid (22 n-blocks, CH_E/128 m-blocks), block 256 (8 warps: wm=wid&3, wn=wid>>2).
// smem: padded bf16 tiles [128][72] x4 (Ahi, Alo, Bhi, Blo) = 73728 B dynamic.
#define TPAD 72

__global__ void __launch_bounds__(256) k_gemm_mma(
    const float* __restrict__ b3, int e_base)
{
    extern __shared__ __nv_bfloat16 sm[];
    __nv_bfloat16* sAhi = sm;
    __nv_bfloat16* sAlo = sm + 128 * TPAD;
    __nv_bfloat16* sBhi = sm + 2 * 128 * TPAD;
    __nv_bfloat16* sBlo = sm + 3 * 128 * TPAD;

    const int t  = threadIdx.x;
    const int n0 = blockIdx.x * 128;
    const int e0 = e_base + blockIdx.y * 128;

    // global -> smem (uint4 = 8 bf16; row stride 72 bf16 = 144 B, 16B-aligned)
    {
        const uint4* gAh = reinterpret_cast<const uint4*>(g_Hhi + (size_t)e0 * 64);
        const uint4* gAl = reinterpret_cast<const uint4*>(g_Hlo + (size_t)e0 * 64);
        const uint4* gBh = reinterpret_cast<const uint4*>(g_w3Thi + (size_t)n0 * 64);
        const uint4* gBl = reinterpret_cast<const uint4*>(g_w3Tlo + (size_t)n0 * 64);
        #pragma unroll
        for (int i = 0; i < 4; ++i) {
            int lin = t + i * 256;                  // 0..1023
            int row = lin >> 3, c8 = lin & 7;
            int dst = row * TPAD + c8 * 8;
            *reinterpret_cast<uint4*>(sAhi + dst) = gAh[lin];
            *reinterpret_cast<uint4*>(sAlo + dst) = gAl[lin];
            *reinterpret_cast<uint4*>(sBhi + dst) = gBh[lin];
            *reinterpret_cast<uint4*>(sBlo + dst) = gBl[lin];
        }
    }
    __syncthreads();

    const int lane = t & 31, wid = t >> 5;
    const int wm = wid & 3, wn = wid >> 2;          // warp tile: rows wm*32+32, cols wn*64+64
    const int g  = lane >> 2, tg = lane & 3;

    float acc[2][8][4];
    #pragma unroll
    for (int mi = 0; mi < 2; ++mi)
        #pragma unroll
        for (int ni = 0; ni < 8; ++ni)
            #pragma unroll
            for (int q = 0; q < 4; ++q) acc[mi][ni][q] = 0.0f;

    #pragma unroll
    for (int ks = 0; ks < 4; ++ks) {
        const int k0 = ks * 16;
        uint32_t ah[2][4], al[2][4];
        #pragma unroll
        for (int mi = 0; mi < 2; ++mi) {
            const int base = (wm * 32 + mi * 16 + g) * TPAD + k0 + tg * 2;
            ah[mi][0] = *reinterpret_cast<const uint32_t*>(sAhi + base);
            ah[mi][1] = *reinterpret_cast<const uint32_t*>(sAhi + base + 8 * TPAD);
            ah[mi][2] = *reinterpret_cast<const uint32_t*>(sAhi + base + 8);
            ah[mi][3] = *reinterpret_cast<const uint32_t*>(sAhi + base + 8 * TPAD + 8);
            al[mi][0] = *reinterpret_cast<const uint32_t*>(sAlo + base);
            al[mi][1] = *reinterpret_cast<const uint32_t*>(sAlo + base + 8 * TPAD);
            al[mi][2] = *reinterpret_cast<const uint32_t*>(sAlo + base + 8);
            al[mi][3] = *reinterpret_cast<const uint32_t*>(sAlo + base + 8 * TPAD + 8);
        }
        #pragma unroll
        for (int ni = 0; ni < 8; ++ni) {
            const int base = (wn * 64 + ni * 8 + g) * TPAD + k0 + tg * 2;
            uint32_t bh[2], bl[2];
            bh[0] = *reinterpret_cast<const uint32_t*>(sBhi + base);
            bh[1] = *reinterpret_cast<const uint32_t*>(sBhi + base + 8);
            bl[0] = *reinterpret_cast<const uint32_t*>(sBlo + base);
            bl[1] = *reinterpret_cast<const uint32_t*>(sBlo + base + 8);
            #pragma unroll
            for (int mi = 0; mi < 2; ++mi) {
                MMA_BF16(acc[mi][ni], ah[mi], bh);
                MMA_BF16(acc[mi][ni], ah[mi], bl);
                MMA_BF16(acc[mi][ni], al[mi], bh);
            }
        }
    }

    // epilogue: add bias, store float2 pairs
    #pragma unroll
    for (int mi = 0; mi < 2; ++mi) {
        const int er = blockIdx.y * 128 + wm * 32 + mi * 16 + g;   // chunk-local edge
        #pragma unroll
        for (int ni = 0; ni < 8; ++ni) {
            const int col = n0 + wn * 64 + ni * 8 + tg * 2;
            const float2 bb = __ldg(reinterpret_cast<const float2*>(b3 + col));
            *reinterpret_cast<float2*>(&g_Wv[(size_t)er * 2816 + col]) =
                make_float2(acc[mi][ni][0] + bb.x, acc[mi][ni][1] + bb.y);
            *reinterpret_cast<float2*>(&g_Wv[(size_t)(er + 8) * 2816 + col]) =
                make_float2(acc[mi][ni][2] + bb.x, acc[mi][ni][3] + bb.y);
        }
    }
}

// ---------------- kernel B2: T-contraction + scatter (unchanged, known-correct) ----
__global__ void __launch_bounds__(256) k_tp2(
    const float* __restrict__ f_in,
    const int* __restrict__ esrc, const int* __restrict__ edst,
    float* __restrict__ out, int e_base)
{
    __shared__ float sT[16][560];
    __shared__ float ssh[16][9];
    __shared__ int   ssrc[16];
    __shared__ int   sdst[16];

    const int tid = threadIdx.x;
    const int e0  = e_base + (blockIdx.x << 4);

    if (tid < 144) ssh[tid / 9][tid % 9] = g_sh[(size_t)e0 * 9 + tid];
    if (tid < 16) ssrc[tid] = esrc[e0 + tid];
    else if (tid < 32) sdst[tid - 16] = edst[e0 + tid - 16];
    __syncthreads();

    {
        const int e = tid >> 4, u = tid & 15;
        const float* x1 = f_in + (size_t)ssrc[e] * 144;
        float xall[9];
        xall[0] = x1[u];
        #pragma unroll
        for (int i = 0; i < 3; ++i) xall[1 + i] = x1[16 + i * 16 + u];
        #pragma unroll
        for (int i = 0; i < 5; ++i) xall[4 + i] = x1[64 + i * 16 + u];
        float sl[9];
        #pragma unroll
        for (int j = 0; j < 9; ++j) sl[j] = ssh[e][j];
        float* Te = sT[e];
        #pragma unroll
        for (int p = 0; p < 11; ++p) {
            const int l1 = PL1[p], l2 = PL2[p];
            const int d1 = 2 * l1 + 1, d2 = 2 * l2 + 1, d3 = PD3[p];
            float acc[5];
            #pragma unroll
            for (int k = 0; k < 5; ++k) acc[k] = 0.0f;
            const float* wj = g_w3j + W3OFF[p];
            #pragma unroll
            for (int i = 0; i < d1; ++i) {
                const float xi = xall[XO[l1] + i];
                #pragma unroll
                for (int j = 0; j < d2; ++j) {
                    const float xs = xi * sl[XO[l2] + j];
                    #pragma unroll
                    for (int k = 0; k < d3; ++k)
                        acc[k] += xs * __ldg(&wj[(i * d2 + j) * d3 + k]);
                }
            }
            #pragma unroll
            for (int k = 0; k < d3; ++k)
                Te[TOFF[p] + u * d3 + k] = ALPHA[p] * acc[k];
        }
    }
    __syncthreads();

    const int e  = tid >> 4;
    const int uh = (tid >> 2) & 3;
    const int wq = tid & 3;
    float4 acc[9];
    #pragma unroll
    for (int a = 0; a < 9; ++a) acc[a] = make_float4(0.f, 0.f, 0.f, 0.f);

    const float4* wv = reinterpret_cast<const float4*>(
        g_Wv + (size_t)((blockIdx.x << 4) + e) * 2816) + wq;
    const float* Te = sT[e];

    #pragma unroll
    for (int p = 0; p < 11; ++p) {
        const int d3 = PD3[p];
        #pragma unroll
        for (int ui = 0; ui < 4; ++ui) {
            const int u = uh * 4 + ui;
            float4 v = __ldg(&wv[(p * 16 + u) * 4]);
            #pragma unroll
            for (int k = 0; k < d3; ++k) {
                const float tv = Te[TOFF[p] + u * d3 + k];
                const int a = AROW[p] + k;
                acc[a].x += tv * v.x; acc[a].y += tv * v.y;
                acc[a].z += tv * v.z; acc[a].w += tv * v.w;
            }
        }
    }

    #pragma unroll
    for (int a = 0; a < 9; ++a) {
        #pragma unroll
        for (int off = 4; off <= 8; off <<= 1) {
            acc[a].x += __shfl_xor_sync(0xffffffffu, acc[a].x, off);
            acc[a].y += __shfl_xor_sync(0xffffffffu, acc[a].y, off);
            acc[a].z += __shfl_xor_sync(0xffffffffu, acc[a].z, off);
            acc[a].w += __shfl_xor_sync(0xffffffffu, acc[a].w, off);
        }
    }
    if (uh == 0) {
        float* op = out + (size_t)sdst[e] * 144 + (wq << 2);
        #pragma unroll
        for (int a = 0; a < 9; ++a) {
            atomicAdd(op + a * 16 + 0, acc[a].x);
            atomicAdd(op + a * 16 + 1, acc[a].y);
            atomicAdd(op + a * 16 + 2, acc[a].z);
            atomicAdd(op + a * 16 + 3, acc[a].w);
        }
    }
}

// ---------------- launch ----------------
extern "C" void kernel_launch(void* const* d_in, const int* in_sizes, int n_in,
                              void* d_out, int out_size)
{
    const float* f_in   = (const float*)d_in[0];
    const float* pos    = (const float*)d_in[1];
    const int*   batch  = (const int*)d_in[3];
    const int*   esrc   = (const int*)d_in[4];
    const int*   edst   = (const int*)d_in[5];
    const float* eshift = (const float*)d_in[6];
    const float* cell   = (const float*)d_in[7];
    const float* w0 = (const float*)d_in[8];
    const float* b0 = (const float*)d_in[9];
    const float* w1 = (const float*)d_in[10];
    const float* b1 = (const float*)d_in[11];
    const float* w2 = (const float*)d_in[12];
    const float* b2 = (const float*)d_in[13];
    const float* w3 = (const float*)d_in[14];
    const float* b3 = (const float*)d_in[15];
    float* out = (float*)d_out;

    const int GEMM_SMEM = 4 * 128 * TPAD * 2;   // 73728 B
    cudaFuncSetAttribute(k_gemm_mma, cudaFuncAttributeMaxDynamicSharedMemorySize, GEMM_SMEM);

    k_init_w3j<<<11, 128>>>();
    k_conv_w3<<<(64 * 2816 + 255) / 256, 256>>>(w3);
    k_zero<<<(NN * 144 + 255) / 256, 256>>>(out);
    k_edge_mlp<<<NE / 4, 256>>>(pos, batch, esrc, edst, eshift, cell,
                                w0, b0, w1, b1, w2, b2);
    k_count<<<(NE + 255) / 256, 256>>>(edst);

    for (int c = 0; c < NCHUNK; ++c) {
        const int e_base = c * CH_E;
        k_gemm_mma<<<dim3(22, CH_E / 128), 256, GEMM_SMEM>>>(b3, e_base);
        k_tp2<<<CH_E / 16, 256>>>(f_in, esrc, edst, out, e_base);
    }

    k_div<<<(NN * 144 + 255) / 256, 256>>>(out);
}